// round 8
// baseline (speedup 1.0000x reference)
#include <cuda_runtime.h>
#include <cstdint>

// ---------------- problem constants ----------------
#define NN0 540672
#define NN1 33792
#define NN2 3072
#define NN3 512
#define EE0 506880
#define EE1 30720
#define EE2 2560
#define FF0 256
#define HH  1024
#define CC  47

// ---------------- device scratch (no allocations allowed) ----------------
__device__ float g_h1[(size_t)NN1 * HH];   // layer-0 output (full precision)
__device__ float g_h2[(size_t)NN2 * HH];   // layer-1 output
__device__ float g_mean0[NN1 * FF0];       // tf32-rounded mean, layer 0
__device__ float g_mean1[NN2 * HH];        // tf32-rounded mean, layer 1
__device__ float g_mean2[NN3 * HH];        // tf32-rounded mean, layer 2
__device__ float g_xr[NN1 * FF0];          // tf32-rounded x prefix
__device__ float g_h1r[NN2 * HH];          // tf32-rounded h1 prefix
// per-layer CSR scratch (separate so layer builds can overlap)
__device__ int g_deg0[NN1], g_off0[NN1], g_cur0[NN1], g_esrc0[EE0];
__device__ int g_deg1[NN2], g_off1[NN2], g_cur1[NN2], g_esrc1[EE1];
__device__ int g_deg2[NN3], g_off2[NN3], g_cur2[NN3], g_esrc2[EE2];
// transposed + tf32-rounded weights, [N][K] K-major
__device__ float g_W0t[2 * HH * FF0];
__device__ float g_W1t[2 * HH * HH];

// ---------------- helpers ----------------
__device__ __forceinline__ uint32_t smem_to_u32(const void* p) {
    uint32_t a;
    asm("{ .reg .u64 t; cvta.to.shared.u64 t, %1; cvt.u32.u64 %0, t; }" : "=r"(a) : "l"(p));
    return a;
}
__device__ __forceinline__ float to_tf32(float x) {
    uint32_t u = __float_as_uint(x), r;
    asm("cvt.rna.tf32.f32 %0, %1;" : "=r"(r) : "r"(u));
    return __uint_as_float(r);
}
__device__ __forceinline__ void cp_async16(uint32_t saddr, const void* gaddr) {
    asm volatile("cp.async.ca.shared.global [%0], [%1], 16;" :: "r"(saddr), "l"(gaddr) : "memory");
}
__device__ __forceinline__ void cp_commit() {
    asm volatile("cp.async.commit_group;" ::: "memory");
}
template <int N>
__device__ __forceinline__ void cp_wait() {
    asm volatile("cp.async.wait_group %0;" :: "n"(N) : "memory");
}
__device__ __forceinline__ void mma_tf32(float* c, const uint32_t* a, const uint32_t* b) {
    asm volatile(
        "mma.sync.aligned.m16n8k8.row.col.f32.tf32.tf32.f32 "
        "{%0,%1,%2,%3}, {%4,%5,%6,%7}, {%8,%9}, {%0,%1,%2,%3};"
        : "+f"(c[0]), "+f"(c[1]), "+f"(c[2]), "+f"(c[3])
        : "r"(a[0]), "r"(a[1]), "r"(a[2]), "r"(a[3]), "r"(b[0]), "r"(b[1]));
}

// ---------------- CSR build (pointer-parameterized) ----------------
__global__ void zero_deg_k(int* __restrict__ deg, int n) {
    int i = blockIdx.x * blockDim.x + threadIdx.x;
    if (i < n) deg[i] = 0;
}
__global__ void count_deg_k(const int* __restrict__ dst, int* __restrict__ deg, int E) {
    int i = blockIdx.x * blockDim.x + threadIdx.x;
    if (i < E) atomicAdd(&deg[dst[i]], 1);
}
__global__ void exscan_k(const int* __restrict__ deg, int* __restrict__ off,
                         int* __restrict__ cur, int n) {
    __shared__ int buf[1024];
    int base = 0;
    for (int start = 0; start < n; start += 1024) {
        int i = start + (int)threadIdx.x;
        int v = (i < n) ? deg[i] : 0;
        __syncthreads();
        buf[threadIdx.x] = v;
        __syncthreads();
        #pragma unroll
        for (int o = 1; o < 1024; o <<= 1) {
            int t = (threadIdx.x >= (unsigned)o) ? buf[threadIdx.x - o] : 0;
            __syncthreads();
            buf[threadIdx.x] += t;
            __syncthreads();
        }
        int incl  = buf[threadIdx.x];
        int total = buf[1023];
        if (i < n) {
            int ex = base + incl - v;
            off[i] = ex;
            cur[i] = ex;
        }
        base += total;
    }
}
__global__ void scatter_k(const int* __restrict__ src, const int* __restrict__ dst,
                          int* __restrict__ cur, int* __restrict__ esrc, int E) {
    int i = blockIdx.x * blockDim.x + threadIdx.x;
    if (i < E) {
        int p = atomicAdd(&cur[dst[i]], 1);
        esrc[p] = src[i];
    }
}

// ---------------- segment mean, tf32-rounded output ----------------
template <int F>
__global__ void aggregate_k(const float* __restrict__ feat,
                            const int* __restrict__ off, const int* __restrict__ deg,
                            const int* __restrict__ esrc, float* __restrict__ out) {
    int v = blockIdx.x;
    int t = threadIdx.x;
    int o = off[v];
    int d = deg[v];
    float4 acc = make_float4(0.f, 0.f, 0.f, 0.f);
    for (int j = 0; j < d; j++) {
        int s = esrc[o + j];
        float4 x = *reinterpret_cast<const float4*>(&feat[(size_t)s * F + t * 4]);
        acc.x += x.x; acc.y += x.y; acc.z += x.z; acc.w += x.w;
    }
    float inv = 1.0f / (float)max(d, 1);
    float4 r;
    r.x = to_tf32(acc.x * inv); r.y = to_tf32(acc.y * inv);
    r.z = to_tf32(acc.z * inv); r.w = to_tf32(acc.w * inv);
    *reinterpret_cast<float4*>(&out[(size_t)v * F + t * 4]) = r;
}

// ---------------- copy + tf32 round (row prefix) ----------------
__global__ void round_copy_k(const float* __restrict__ in, float* __restrict__ out, int n4) {
    int i = blockIdx.x * blockDim.x + threadIdx.x;
    if (i < n4) {
        float4 v = reinterpret_cast<const float4*>(in)[i];
        v.x = to_tf32(v.x); v.y = to_tf32(v.y); v.z = to_tf32(v.z); v.w = to_tf32(v.w);
        reinterpret_cast<float4*>(out)[i] = v;
    }
}

// ---------------- weight transpose + tf32 round: W[K,N] -> Wt[N,K] ----------------
__global__ void transpose_cvt_k(const float* __restrict__ W, float* __restrict__ Wt,
                                int K, int N) {
    __shared__ float tile[32][33];
    int n0 = blockIdx.x * 32, k0 = blockIdx.y * 32;
    tile[threadIdx.y][threadIdx.x] = W[(size_t)(k0 + threadIdx.y) * N + n0 + threadIdx.x];
    __syncthreads();
    Wt[(size_t)(n0 + threadIdx.y) * K + k0 + threadIdx.x] = to_tf32(tile[threadIdx.x][threadIdx.y]);
}

// ---------------- TF32 mma.sync dual GEMM ----------------
// C[M,N] = act(A1@W1 + A2@W2 + bias); A tf32-rounded fp32 row-major [M,K],
// B tf32 [N,K] K-major. 128x128 CTA tile, BK=32, 256 threads (2x4 warps),
// 2-stage cp.async pipeline. M%128==0, N%128==0, K%32==0.
static constexpr int GSTRIDE = 36;
static constexpr int ATILE   = 128 * GSTRIDE;
static constexpr int STAGE   = 2 * ATILE;
static constexpr int SM_BYTES = 2 * STAGE * 4;   // 73728

template <bool RELU>
__global__ __launch_bounds__(256, 2)
void gemm_mma_k(const float* __restrict__ A1, const float* __restrict__ A2,
                const float* __restrict__ B1t, const float* __restrict__ B2t,
                const float* __restrict__ bias, float* __restrict__ C,
                int M, int N, int K) {
    extern __shared__ float smf[];
    const uint32_t sbase = smem_to_u32(smf);
    const int tid  = threadIdx.x;
    const int wid  = tid >> 5;
    const int lane = tid & 31;
    const int wm   = wid >> 2;
    const int wn   = wid & 3;
    const int g    = lane >> 2;
    const int tig  = lane & 3;
    const int bm   = blockIdx.y * 128;
    const int bn   = blockIdx.x * 128;

    const int ldrow = tid >> 3;
    const int ldseg = tid & 7;

    float acc[4][4][4];
    #pragma unroll
    for (int mt = 0; mt < 4; mt++)
        #pragma unroll
        for (int nt = 0; nt < 4; nt++)
            #pragma unroll
            for (int i = 0; i < 4; i++) acc[mt][nt][i] = 0.f;

    const int kt = K / 32;
    const int T  = 2 * kt;

    auto issue_load = [&](int t, int s) {
        int pass = t >= kt;
        int k0 = (t - pass * kt) * 32;
        const float* __restrict__ A = pass ? A2 : A1;
        const float* __restrict__ B = pass ? B2t : B1t;
        uint32_t abase = sbase + (uint32_t)(s * STAGE) * 4;
        uint32_t bbase = abase + (uint32_t)ATILE * 4;
        #pragma unroll
        for (int i = 0; i < 4; i++) {
            int row = ldrow + i * 32;
            uint32_t off = (uint32_t)(row * GSTRIDE + ldseg * 4) * 4;
            cp_async16(abase + off, &A[(size_t)(bm + row) * K + k0 + ldseg * 4]);
            cp_async16(bbase + off, &B[(size_t)(bn + row) * K + k0 + ldseg * 4]);
        }
        cp_commit();
    };

    issue_load(0, 0);

    for (int t = 0; t < T; t++) {
        int s = t & 1;
        if (t + 1 < T) { issue_load(t + 1, s ^ 1); cp_wait<1>(); }
        else           { cp_wait<0>(); }
        __syncthreads();

        const float* As = smf + s * STAGE;
        const float* Bs = As + ATILE;
        #pragma unroll
        for (int kc = 0; kc < 32; kc += 8) {
            uint32_t a[4][4], b[4][2];
            #pragma unroll
            for (int mt = 0; mt < 4; mt++) {
                int rb = wm * 64 + mt * 16 + g;
                a[mt][0] = __float_as_uint(As[(rb    ) * GSTRIDE + kc + tig    ]);
                a[mt][1] = __float_as_uint(As[(rb + 8) * GSTRIDE + kc + tig    ]);
                a[mt][2] = __float_as_uint(As[(rb    ) * GSTRIDE + kc + tig + 4]);
                a[mt][3] = __float_as_uint(As[(rb + 8) * GSTRIDE + kc + tig + 4]);
            }
            #pragma unroll
            for (int nt = 0; nt < 4; nt++) {
                int nb = wn * 32 + nt * 8 + g;
                b[nt][0] = __float_as_uint(Bs[nb * GSTRIDE + kc + tig    ]);
                b[nt][1] = __float_as_uint(Bs[nb * GSTRIDE + kc + tig + 4]);
            }
            #pragma unroll
            for (int mt = 0; mt < 4; mt++)
                #pragma unroll
                for (int nt = 0; nt < 4; nt++)
                    mma_tf32(acc[mt][nt], a[mt], b[nt]);
        }
        __syncthreads();   // reads of stage s done before next issue overwrites it
    }

    #pragma unroll
    for (int mt = 0; mt < 4; mt++) {
        int r0 = bm + wm * 64 + mt * 16 + g;
        #pragma unroll
        for (int nt = 0; nt < 4; nt++) {
            int c = bn + wn * 32 + nt * 8 + 2 * tig;
            float bx = __ldg(&bias[c]), by = __ldg(&bias[c + 1]);
            float2 v0 = make_float2(acc[mt][nt][0] + bx, acc[mt][nt][1] + by);
            float2 v1 = make_float2(acc[mt][nt][2] + bx, acc[mt][nt][3] + by);
            if (RELU) {
                v0.x = fmaxf(v0.x, 0.f); v0.y = fmaxf(v0.y, 0.f);
                v1.x = fmaxf(v1.x, 0.f); v1.y = fmaxf(v1.y, 0.f);
            }
            *reinterpret_cast<float2*>(&C[(size_t)r0 * N + c]) = v0;
            *reinterpret_cast<float2*>(&C[(size_t)(r0 + 8) * N + c]) = v1;
        }
    }
}

// ---------------- small final GEMM (N=47) ----------------
__global__ void gemm_small_k(const float* __restrict__ A1, const float* __restrict__ A2,
                             const float* __restrict__ B1, const float* __restrict__ B2,
                             const float* __restrict__ bias, float* __restrict__ C,
                             int K, int N) {
    __shared__ float a1[HH];
    __shared__ float a2[HH];
    int m = blockIdx.x;
    for (int i = threadIdx.x; i < K; i += blockDim.x) {
        a1[i] = A1[(size_t)m * K + i];
        a2[i] = A2[(size_t)m * K + i];
    }
    __syncthreads();
    for (int c = threadIdx.x; c < N; c += blockDim.x) {
        float s = bias[c];
        #pragma unroll 8
        for (int k = 0; k < K; k++)
            s += a1[k] * B1[(size_t)k * N + c] + a2[k] * B2[(size_t)k * N + c];
        C[(size_t)m * N + c] = s;
    }
}

// ---------------- launch ----------------
extern "C" void kernel_launch(void* const* d_in, const int* in_sizes, int n_in,
                              void* d_out, int out_size) {
    const float* x   = (const float*)d_in[0];
    const int* src0  = (const int*)d_in[1];
    const int* dst0  = (const int*)d_in[2];
    const int* src1  = (const int*)d_in[3];
    const int* dst1  = (const int*)d_in[4];
    const int* src2  = (const int*)d_in[5];
    const int* dst2  = (const int*)d_in[6];
    const float* Ws0 = (const float*)d_in[7];
    const float* Wn0 = (const float*)d_in[8];
    const float* b0  = (const float*)d_in[9];
    const float* Ws1 = (const float*)d_in[10];
    const float* Wn1 = (const float*)d_in[11];
    const float* b1  = (const float*)d_in[12];
    const float* Ws2 = (const float*)d_in[13];
    const float* Wn2 = (const float*)d_in[14];
    const float* b2  = (const float*)d_in[15];
    float* out = (float*)d_out;

    float *h1_p, *h2_p, *m0_p, *m1_p, *m2_p, *xr_p, *h1r_p, *w0t_p, *w1t_p;
    int *deg0, *off0, *cur0, *es0, *deg1, *off1, *cur1, *es1, *deg2, *off2, *cur2, *es2;
    cudaGetSymbolAddress((void**)&h1_p, g_h1);
    cudaGetSymbolAddress((void**)&h2_p, g_h2);
    cudaGetSymbolAddress((void**)&m0_p, g_mean0);
    cudaGetSymbolAddress((void**)&m1_p, g_mean1);
    cudaGetSymbolAddress((void**)&m2_p, g_mean2);
    cudaGetSymbolAddress((void**)&xr_p, g_xr);
    cudaGetSymbolAddress((void**)&h1r_p, g_h1r);
    cudaGetSymbolAddress((void**)&w0t_p, g_W0t);
    cudaGetSymbolAddress((void**)&w1t_p, g_W1t);
    cudaGetSymbolAddress((void**)&deg0, g_deg0); cudaGetSymbolAddress((void**)&off0, g_off0);
    cudaGetSymbolAddress((void**)&cur0, g_cur0); cudaGetSymbolAddress((void**)&es0, g_esrc0);
    cudaGetSymbolAddress((void**)&deg1, g_deg1); cudaGetSymbolAddress((void**)&off1, g_off1);
    cudaGetSymbolAddress((void**)&cur1, g_cur1); cudaGetSymbolAddress((void**)&es1, g_esrc1);
    cudaGetSymbolAddress((void**)&deg2, g_deg2); cudaGetSymbolAddress((void**)&off2, g_off2);
    cudaGetSymbolAddress((void**)&cur2, g_cur2); cudaGetSymbolAddress((void**)&es2, g_esrc2);

    static cudaStream_t sW = nullptr, sC = nullptr;
    static cudaEvent_t eIn, eW, eC1, eC2;
    static int inited = 0;
    if (!inited) {
        cudaFuncSetAttribute(gemm_mma_k<true>,
                             cudaFuncAttributeMaxDynamicSharedMemorySize, SM_BYTES);
        cudaFuncSetAttribute(gemm_mma_k<false>,
                             cudaFuncAttributeMaxDynamicSharedMemorySize, SM_BYTES);
        cudaStreamCreateWithFlags(&sW, cudaStreamNonBlocking);
        cudaStreamCreateWithFlags(&sC, cudaStreamNonBlocking);
        cudaEventCreateWithFlags(&eIn, cudaEventDisableTiming);
        cudaEventCreateWithFlags(&eW,  cudaEventDisableTiming);
        cudaEventCreateWithFlags(&eC1, cudaEventDisableTiming);
        cudaEventCreateWithFlags(&eC2, cudaEventDisableTiming);
        inited = 1;
    }

    cudaEventRecord(eIn, 0);

    // ---- branch W (stream sW): weight prep + x-prefix rounding ----
    cudaStreamWaitEvent(sW, eIn, 0);
    {
        dim3 blk(32, 32);
        transpose_cvt_k<<<dim3(HH / 32, FF0 / 32), blk, 0, sW>>>(Ws0, w0t_p, FF0, HH);
        transpose_cvt_k<<<dim3(HH / 32, FF0 / 32), blk, 0, sW>>>(Wn0, w0t_p + HH * FF0, FF0, HH);
        transpose_cvt_k<<<dim3(HH / 32, HH / 32), blk, 0, sW>>>(Ws1, w1t_p, HH, HH);
        transpose_cvt_k<<<dim3(HH / 32, HH / 32), blk, 0, sW>>>(Wn1, w1t_p + HH * HH, HH, HH);
        int n4 = NN1 * FF0 / 4;
        round_copy_k<<<(n4 + 255) / 256, 256, 0, sW>>>(x, xr_p, n4);
    }
    cudaEventRecord(eW, sW);

    // ---- branch C (stream sC): CSR builds for layers 1 and 2 ----
    cudaStreamWaitEvent(sC, eIn, 0);
    zero_deg_k<<<(NN2 + 255) / 256, 256, 0, sC>>>(deg1, NN2);
    count_deg_k<<<(EE1 + 255) / 256, 256, 0, sC>>>(dst1, deg1, EE1);
    exscan_k<<<1, 1024, 0, sC>>>(deg1, off1, cur1, NN2);
    scatter_k<<<(EE1 + 255) / 256, 256, 0, sC>>>(src1, dst1, cur1, es1, EE1);
    cudaEventRecord(eC1, sC);
    zero_deg_k<<<(NN3 + 255) / 256, 256, 0, sC>>>(deg2, NN3);
    count_deg_k<<<(EE2 + 255) / 256, 256, 0, sC>>>(dst2, deg2, EE2);
    exscan_k<<<1, 1024, 0, sC>>>(deg2, off2, cur2, NN3);
    scatter_k<<<(EE2 + 255) / 256, 256, 0, sC>>>(src2, dst2, cur2, es2, EE2);
    cudaEventRecord(eC2, sC);

    // ---- main chain: layer 0 CSR + aggregate ----
    zero_deg_k<<<(NN1 + 255) / 256, 256>>>(deg0, NN1);
    count_deg_k<<<(EE0 + 255) / 256, 256>>>(dst0, deg0, EE0);
    exscan_k<<<1, 1024>>>(deg0, off0, cur0, NN1);
    scatter_k<<<(EE0 + 255) / 256, 256>>>(src0, dst0, cur0, es0, EE0);
    aggregate_k<FF0><<<NN1, FF0 / 4>>>(x, off0, deg0, es0, m0_p);

    cudaStreamWaitEvent(0, eW, 0);
    gemm_mma_k<true><<<dim3(HH / 128, NN1 / 128), 256, SM_BYTES>>>(
        xr_p, m0_p, w0t_p, w0t_p + HH * FF0, b0, h1_p, NN1, HH, FF0);

    // round h1 prefix for next GEMM's A1
    {
        int n4 = NN2 * HH / 4;
        round_copy_k<<<(n4 + 255) / 256, 256>>>(h1_p, h1r_p, n4);
    }

    cudaStreamWaitEvent(0, eC1, 0);
    aggregate_k<HH><<<NN2, HH / 4>>>(h1_p, off1, deg1, es1, m1_p);
    gemm_mma_k<true><<<dim3(HH / 128, NN2 / 128), 256, SM_BYTES>>>(
        h1r_p, m1_p, w1t_p, w1t_p + HH * HH, b1, h2_p, NN2, HH, HH);

    cudaStreamWaitEvent(0, eC2, 0);
    aggregate_k<HH><<<NN3, HH / 4>>>(h2_p, off2, deg2, es2, m2_p);
    gemm_small_k<<<NN3, 128>>>(h2_p, m2_p, Ws2, Wn2, b2, out, HH, CC);
}

// round 12
// speedup vs baseline: 1.2813x; 1.2813x over previous
#include <cuda_runtime.h>
#include <cstdint>

// ---------------- problem constants ----------------
#define NN0 540672
#define NN1 33792
#define NN2 3072
#define NN3 512
#define EE0 506880
#define EE1 30720
#define EE2 2560
#define FF0 256
#define HH  1024
#define CC  47

// ---------------- device scratch (no allocations allowed) ----------------
__device__ float g_h1[(size_t)NN1 * HH];   // layer-0 output (full precision)
__device__ float g_h2[(size_t)NN2 * HH];   // layer-1 output
__device__ float g_mean[NN1 * FF0];        // tf32-rounded mean (reused per layer)
__device__ float g_xr[NN1 * FF0];          // tf32-rounded x prefix
__device__ float g_h1r[NN2 * HH];          // tf32-rounded h1 prefix
__device__ int   g_deg[NN1];
__device__ int   g_off[NN1];
__device__ int   g_cur[NN1];
__device__ int   g_esrc[EE0];
// transposed + tf32-rounded weights, [N][K] K-major
__device__ float g_W0t[2 * HH * FF0];
__device__ float g_W1t[2 * HH * HH];

// ---------------- helpers ----------------
__device__ __forceinline__ uint32_t smem_to_u32(const void* p) {
    uint32_t a;
    asm("{ .reg .u64 t; cvta.to.shared.u64 t, %1; cvt.u32.u64 %0, t; }" : "=r"(a) : "l"(p));
    return a;
}
__device__ __forceinline__ float to_tf32(float x) {
    uint32_t u = __float_as_uint(x), r;
    asm("cvt.rna.tf32.f32 %0, %1;" : "=r"(r) : "r"(u));
    return __uint_as_float(r);
}
__device__ __forceinline__ void cp_async16(uint32_t saddr, const void* gaddr) {
    asm volatile("cp.async.ca.shared.global [%0], [%1], 16;" :: "r"(saddr), "l"(gaddr) : "memory");
}
__device__ __forceinline__ void cp_commit() {
    asm volatile("cp.async.commit_group;" ::: "memory");
}
template <int N>
__device__ __forceinline__ void cp_wait() {
    asm volatile("cp.async.wait_group %0;" :: "n"(N) : "memory");
}
__device__ __forceinline__ void mma_tf32(float* c, const uint32_t* a, const uint32_t* b) {
    asm volatile(
        "mma.sync.aligned.m16n8k8.row.col.f32.tf32.tf32.f32 "
        "{%0,%1,%2,%3}, {%4,%5,%6,%7}, {%8,%9}, {%0,%1,%2,%3};"
        : "+f"(c[0]), "+f"(c[1]), "+f"(c[2]), "+f"(c[3])
        : "r"(a[0]), "r"(a[1]), "r"(a[2]), "r"(a[3]), "r"(b[0]), "r"(b[1]));
}

// ---------------- CSR build ----------------
__global__ void zero_deg_k(int n) {
    int i = blockIdx.x * blockDim.x + threadIdx.x;
    if (i < n) g_deg[i] = 0;
}
__global__ void count_deg_k(const int* __restrict__ dst, int E) {
    int i = blockIdx.x * blockDim.x + threadIdx.x;
    if (i < E) atomicAdd(&g_deg[dst[i]], 1);
}
__global__ void exscan_k(int n) {
    __shared__ int buf[1024];
    int base = 0;
    for (int start = 0; start < n; start += 1024) {
        int i = start + (int)threadIdx.x;
        int v = (i < n) ? g_deg[i] : 0;
        __syncthreads();
        buf[threadIdx.x] = v;
        __syncthreads();
        #pragma unroll
        for (int o = 1; o < 1024; o <<= 1) {
            int t = (threadIdx.x >= (unsigned)o) ? buf[threadIdx.x - o] : 0;
            __syncthreads();
            buf[threadIdx.x] += t;
            __syncthreads();
        }
        int incl  = buf[threadIdx.x];
        int total = buf[1023];
        if (i < n) {
            int ex = base + incl - v;
            g_off[i] = ex;
            g_cur[i] = ex;
        }
        base += total;
    }
}
__global__ void scatter_k(const int* __restrict__ src, const int* __restrict__ dst, int E) {
    int i = blockIdx.x * blockDim.x + threadIdx.x;
    if (i < E) {
        int p = atomicAdd(&g_cur[dst[i]], 1);
        g_esrc[p] = src[i];
    }
}

// ---------------- segment mean, tf32-rounded output ----------------
template <int F>
__global__ void aggregate_k(const float* __restrict__ feat, float* __restrict__ out) {
    int v = blockIdx.x;
    int t = threadIdx.x;
    int o = g_off[v];
    int d = g_deg[v];
    float4 acc = make_float4(0.f, 0.f, 0.f, 0.f);
    for (int j = 0; j < d; j++) {
        int s = g_esrc[o + j];
        float4 x = *reinterpret_cast<const float4*>(&feat[(size_t)s * F + t * 4]);
        acc.x += x.x; acc.y += x.y; acc.z += x.z; acc.w += x.w;
    }
    float inv = 1.0f / (float)max(d, 1);
    float4 r;
    r.x = to_tf32(acc.x * inv); r.y = to_tf32(acc.y * inv);
    r.z = to_tf32(acc.z * inv); r.w = to_tf32(acc.w * inv);
    *reinterpret_cast<float4*>(&out[(size_t)v * F + t * 4]) = r;
}

// ---------------- copy + tf32 round (row prefix) ----------------
__global__ void round_copy_k(const float* __restrict__ in, float* __restrict__ out, int n4) {
    int i = blockIdx.x * blockDim.x + threadIdx.x;
    if (i < n4) {
        float4 v = reinterpret_cast<const float4*>(in)[i];
        v.x = to_tf32(v.x); v.y = to_tf32(v.y); v.z = to_tf32(v.z); v.w = to_tf32(v.w);
        reinterpret_cast<float4*>(out)[i] = v;
    }
}

// ---------------- weight transpose + tf32 round: W[K,N] -> Wt[N,K] ----------------
__global__ void transpose_cvt_k(const float* __restrict__ W, float* __restrict__ Wt,
                                int K, int N) {
    __shared__ float tile[32][33];
    int n0 = blockIdx.x * 32, k0 = blockIdx.y * 32;
    tile[threadIdx.y][threadIdx.x] = W[(size_t)(k0 + threadIdx.y) * N + n0 + threadIdx.x];
    __syncthreads();
    Wt[(size_t)(n0 + threadIdx.y) * K + k0 + threadIdx.x] = to_tf32(tile[threadIdx.x][threadIdx.y]);
}

// ---------------- TF32 mma.sync dual GEMM ----------------
// C[M,N] = act(A1@W1 + A2@W2 + bias); all operands pre-rounded to tf32.
// A fp32 row-major [M,K], B tf32 [N,K] K-major. 128x128 CTA tile, BK=32,
// 256 threads (2x4 warps), 2-stage cp.async pipeline. M%128==0, N%128==0, K%32==0.
// Optional secondary output: rows < M2 also stored tf32-rounded to C2.
static constexpr int GSTRIDE = 36;
static constexpr int ATILE   = 128 * GSTRIDE;
static constexpr int STAGE   = 2 * ATILE;
static constexpr int SM_BYTES = 2 * STAGE * 4;   // 73728

template <bool RELU>
__global__ __launch_bounds__(256)
void gemm_mma_k(const float* __restrict__ A1, const float* __restrict__ A2,
                const float* __restrict__ B1t, const float* __restrict__ B2t,
                const float* __restrict__ bias, float* __restrict__ C,
                float* __restrict__ C2, int M2,
                int M, int N, int K) {
    extern __shared__ float smf[];
    const uint32_t sbase = smem_to_u32(smf);
    const int tid  = threadIdx.x;
    const int wid  = tid >> 5;
    const int lane = tid & 31;
    const int wm   = wid >> 2;
    const int wn   = wid & 3;
    const int g    = lane >> 2;
    const int tig  = lane & 3;
    const int bm   = blockIdx.y * 128;
    const int bn   = blockIdx.x * 128;

    const int ldrow = tid >> 3;
    const int ldseg = tid & 7;

    float acc[4][4][4];
    #pragma unroll
    for (int mt = 0; mt < 4; mt++)
        #pragma unroll
        for (int nt = 0; nt < 4; nt++)
            #pragma unroll
            for (int i = 0; i < 4; i++) acc[mt][nt][i] = 0.f;

    const int kt = K / 32;
    const int T  = 2 * kt;

    auto issue_load = [&](int t, int s) {
        int pass = t >= kt;
        int k0 = (t - pass * kt) * 32;
        const float* __restrict__ A = pass ? A2 : A1;
        const float* __restrict__ B = pass ? B2t : B1t;
        uint32_t abase = sbase + (uint32_t)(s * STAGE) * 4;
        uint32_t bbase = abase + (uint32_t)ATILE * 4;
        #pragma unroll
        for (int i = 0; i < 4; i++) {
            int row = ldrow + i * 32;
            uint32_t off = (uint32_t)(row * GSTRIDE + ldseg * 4) * 4;
            cp_async16(abase + off, &A[(size_t)(bm + row) * K + k0 + ldseg * 4]);
            cp_async16(bbase + off, &B[(size_t)(bn + row) * K + k0 + ldseg * 4]);
        }
        cp_commit();
    };

    issue_load(0, 0);

    for (int t = 0; t < T; t++) {
        int s = t & 1;
        if (t + 1 < T) { issue_load(t + 1, s ^ 1); cp_wait<1>(); }
        else           { cp_wait<0>(); }
        __syncthreads();

        const float* As = smf + s * STAGE;
        const float* Bs = As + ATILE;
        #pragma unroll
        for (int kc = 0; kc < 32; kc += 8) {
            uint32_t a[4][4], b[4][2];
            #pragma unroll
            for (int mt = 0; mt < 4; mt++) {
                int rb = wm * 64 + mt * 16 + g;
                a[mt][0] = __float_as_uint(As[(rb    ) * GSTRIDE + kc + tig    ]);
                a[mt][1] = __float_as_uint(As[(rb + 8) * GSTRIDE + kc + tig    ]);
                a[mt][2] = __float_as_uint(As[(rb    ) * GSTRIDE + kc + tig + 4]);
                a[mt][3] = __float_as_uint(As[(rb + 8) * GSTRIDE + kc + tig + 4]);
            }
            #pragma unroll
            for (int nt = 0; nt < 4; nt++) {
                int nb = wn * 32 + nt * 8 + g;
                b[nt][0] = __float_as_uint(Bs[nb * GSTRIDE + kc + tig    ]);
                b[nt][1] = __float_as_uint(Bs[nb * GSTRIDE + kc + tig + 4]);
            }
            #pragma unroll
            for (int mt = 0; mt < 4; mt++)
                #pragma unroll
                for (int nt = 0; nt < 4; nt++)
                    mma_tf32(acc[mt][nt], a[mt], b[nt]);
        }
        __syncthreads();   // reads of stage s done before next issue overwrites it
    }

    #pragma unroll
    for (int mt = 0; mt < 4; mt++) {
        int r0 = bm + wm * 64 + mt * 16 + g;
        #pragma unroll
        for (int nt = 0; nt < 4; nt++) {
            int c = bn + wn * 32 + nt * 8 + 2 * tig;
            float bx = __ldg(&bias[c]), by = __ldg(&bias[c + 1]);
            float2 v0 = make_float2(acc[mt][nt][0] + bx, acc[mt][nt][1] + by);
            float2 v1 = make_float2(acc[mt][nt][2] + bx, acc[mt][nt][3] + by);
            if (RELU) {
                v0.x = fmaxf(v0.x, 0.f); v0.y = fmaxf(v0.y, 0.f);
                v1.x = fmaxf(v1.x, 0.f); v1.y = fmaxf(v1.y, 0.f);
            }
            *reinterpret_cast<float2*>(&C[(size_t)r0 * N + c]) = v0;
            *reinterpret_cast<float2*>(&C[(size_t)(r0 + 8) * N + c]) = v1;
            if (C2 != nullptr && r0 < M2) {
                // rows r0 and r0+8 are in the same 16-row tile; M2 % 128 == 0
                float2 w0 = make_float2(to_tf32(v0.x), to_tf32(v0.y));
                float2 w1 = make_float2(to_tf32(v1.x), to_tf32(v1.y));
                *reinterpret_cast<float2*>(&C2[(size_t)r0 * N + c]) = w0;
                *reinterpret_cast<float2*>(&C2[(size_t)(r0 + 8) * N + c]) = w1;
            }
        }
    }
}

// ---------------- small final GEMM (N=47) ----------------
__global__ void gemm_small_k(const float* __restrict__ A1, const float* __restrict__ A2,
                             const float* __restrict__ B1, const float* __restrict__ B2,
                             const float* __restrict__ bias, float* __restrict__ C,
                             int K, int N) {
    __shared__ float a1[HH];
    __shared__ float a2[HH];
    int m = blockIdx.x;
    for (int i = threadIdx.x; i < K; i += blockDim.x) {
        a1[i] = A1[(size_t)m * K + i];
        a2[i] = A2[(size_t)m * K + i];
    }
    __syncthreads();
    for (int c = threadIdx.x; c < N; c += blockDim.x) {
        float s = bias[c];
        #pragma unroll 8
        for (int k = 0; k < K; k++)
            s += a1[k] * B1[(size_t)k * N + c] + a2[k] * B2[(size_t)k * N + c];
        C[(size_t)m * N + c] = s;
    }
}

// ---------------- launch ----------------
extern "C" void kernel_launch(void* const* d_in, const int* in_sizes, int n_in,
                              void* d_out, int out_size) {
    const float* x   = (const float*)d_in[0];
    const int* src0  = (const int*)d_in[1];
    const int* dst0  = (const int*)d_in[2];
    const int* src1  = (const int*)d_in[3];
    const int* dst1  = (const int*)d_in[4];
    const int* src2  = (const int*)d_in[5];
    const int* dst2  = (const int*)d_in[6];
    const float* Ws0 = (const float*)d_in[7];
    const float* Wn0 = (const float*)d_in[8];
    const float* b0  = (const float*)d_in[9];
    const float* Ws1 = (const float*)d_in[10];
    const float* Wn1 = (const float*)d_in[11];
    const float* b1  = (const float*)d_in[12];
    const float* Ws2 = (const float*)d_in[13];
    const float* Wn2 = (const float*)d_in[14];
    const float* b2  = (const float*)d_in[15];
    float* out = (float*)d_out;

    float *h1_p, *h2_p, *m_p, *xr_p, *h1r_p, *w0t_p, *w1t_p;
    cudaGetSymbolAddress((void**)&h1_p, g_h1);
    cudaGetSymbolAddress((void**)&h2_p, g_h2);
    cudaGetSymbolAddress((void**)&m_p, g_mean);
    cudaGetSymbolAddress((void**)&xr_p, g_xr);
    cudaGetSymbolAddress((void**)&h1r_p, g_h1r);
    cudaGetSymbolAddress((void**)&w0t_p, g_W0t);
    cudaGetSymbolAddress((void**)&w1t_p, g_W1t);

    static int inited = 0;
    if (!inited) {
        cudaFuncSetAttribute(gemm_mma_k<true>,
                             cudaFuncAttributeMaxDynamicSharedMemorySize, SM_BYTES);
        cudaFuncSetAttribute(gemm_mma_k<false>,
                             cudaFuncAttributeMaxDynamicSharedMemorySize, SM_BYTES);
        inited = 1;
    }

    // ---- weight prep + x-prefix rounding ----
    {
        dim3 blk(32, 32);
        transpose_cvt_k<<<dim3(HH / 32, FF0 / 32), blk>>>(Ws0, w0t_p, FF0, HH);
        transpose_cvt_k<<<dim3(HH / 32, FF0 / 32), blk>>>(Wn0, w0t_p + HH * FF0, FF0, HH);
        transpose_cvt_k<<<dim3(HH / 32, HH / 32), blk>>>(Ws1, w1t_p, HH, HH);
        transpose_cvt_k<<<dim3(HH / 32, HH / 32), blk>>>(Wn1, w1t_p + HH * HH, HH, HH);
        int n4 = NN1 * FF0 / 4;
        round_copy_k<<<(n4 + 255) / 256, 256>>>(x, xr_p, n4);
    }

    // ---- Layer 0: x[N0,256] -> h1[N1,1024], ReLU; also emits rounded h1 prefix ----
    zero_deg_k<<<(NN1 + 255) / 256, 256>>>(NN1);
    count_deg_k<<<(EE0 + 255) / 256, 256>>>(dst0, EE0);
    exscan_k<<<1, 1024>>>(NN1);
    scatter_k<<<(EE0 + 255) / 256, 256>>>(src0, dst0, EE0);
    aggregate_k<FF0><<<NN1, FF0 / 4>>>(x, m_p);
    gemm_mma_k<true><<<dim3(HH / 128, NN1 / 128), 256, SM_BYTES>>>(
        xr_p, m_p, w0t_p, w0t_p + HH * FF0, b0, h1_p, h1r_p, NN2, NN1, HH, FF0);

    // ---- Layer 1: h1[N1,1024] -> h2[N2,1024], ReLU ----
    zero_deg_k<<<(NN2 + 255) / 256, 256>>>(NN2);
    count_deg_k<<<(EE1 + 255) / 256, 256>>>(dst1, EE1);
    exscan_k<<<1, 1024>>>(NN2);
    scatter_k<<<(EE1 + 255) / 256, 256>>>(src1, dst1, EE1);
    aggregate_k<HH><<<NN2, HH / 4>>>(h1_p, m_p);
    gemm_mma_k<true><<<dim3(HH / 128, NN2 / 128), 256, SM_BYTES>>>(
        h1r_p, m_p, w1t_p, w1t_p + HH * HH, b1, h2_p, (float*)nullptr, 0, NN2, HH, HH);

    // ---- Layer 2: h2[N2,1024] -> out[N3,47], no activation ----
    zero_deg_k<<<(NN3 + 255) / 256, 256>>>(NN3);
    count_deg_k<<<(EE2 + 255) / 256, 256>>>(dst2, EE2);
    exscan_k<<<1, 1024>>>(NN3);
    scatter_k<<<(EE2 + 255) / 256, 256>>>(src2, dst2, EE2);
    aggregate_k<HH><<<NN3, HH / 4>>>(h2_p, m_p);
    gemm_small_k<<<NN3, 128>>>(h2_p, m_p, Ws2, Wn2, b2, out, HH, CC);
}

// round 13
// speedup vs baseline: 1.5752x; 1.2294x over previous
#include <cuda_runtime.h>
#include <cuda_fp16.h>
#include <cstdint>

// ---------------- problem constants ----------------
#define NN0 540672
#define NN1 33792
#define NN2 3072
#define NN3 512
#define EE0 506880
#define EE1 30720
#define EE2 2560
#define FF0 256
#define HH  1024
#define CC  47

// ---------------- device scratch (no allocations allowed) ----------------
__device__ float  g_h1[(size_t)NN1 * HH];   // layer-0 output (fp32, for L1 aggregate)
__device__ float  g_h2[(size_t)NN2 * HH];   // layer-1 output (fp32, for L2)
__device__ float  g_mean[NN3 * HH];         // fp32 mean for layer 2
__device__ __half g_meanh[NN1 * FF0];       // fp16 mean (L0: NN1*256; L1 reuse: NN2*1024)
__device__ __half g_xh[NN1 * FF0];          // fp16 x prefix
__device__ __half g_h1h[NN2 * HH];          // fp16 h1 prefix
__device__ int    g_deg[NN1];
__device__ int    g_off[NN1];
__device__ int    g_cur[NN1];
__device__ int    g_esrc[EE0];
// transposed fp16 weights, [N][K] K-major
__device__ __half g_W0t[2 * HH * FF0];
__device__ __half g_W1t[2 * HH * HH];

// ---------------- helpers ----------------
__device__ __forceinline__ uint32_t smem_to_u32(const void* p) {
    uint32_t a;
    asm("{ .reg .u64 t; cvta.to.shared.u64 t, %1; cvt.u32.u64 %0, t; }" : "=r"(a) : "l"(p));
    return a;
}
__device__ __forceinline__ void cp_async16(uint32_t saddr, const void* gaddr) {
    asm volatile("cp.async.ca.shared.global [%0], [%1], 16;" :: "r"(saddr), "l"(gaddr) : "memory");
}
__device__ __forceinline__ void cp_commit() {
    asm volatile("cp.async.commit_group;" ::: "memory");
}
template <int N>
__device__ __forceinline__ void cp_wait() {
    asm volatile("cp.async.wait_group %0;" :: "n"(N) : "memory");
}
// m16n8k16 fp16 MMA, fp32 accumulate
__device__ __forceinline__ void mma_f16(float* c, const uint32_t* a, const uint32_t* b) {
    asm volatile(
        "mma.sync.aligned.m16n8k16.row.col.f32.f16.f16.f32 "
        "{%0,%1,%2,%3}, {%4,%5,%6,%7}, {%8,%9}, {%0,%1,%2,%3};"
        : "+f"(c[0]), "+f"(c[1]), "+f"(c[2]), "+f"(c[3])
        : "r"(a[0]), "r"(a[1]), "r"(a[2]), "r"(a[3]), "r"(b[0]), "r"(b[1]));
}

// ---------------- CSR build ----------------
__global__ void zero_deg_k(int n) {
    int i = blockIdx.x * blockDim.x + threadIdx.x;
    if (i < n) g_deg[i] = 0;
}
__global__ void count_deg_k(const int* __restrict__ dst, int E) {
    int i = blockIdx.x * blockDim.x + threadIdx.x;
    if (i < E) atomicAdd(&g_deg[dst[i]], 1);
}
__global__ void exscan_k(int n) {
    __shared__ int buf[1024];
    int base = 0;
    for (int start = 0; start < n; start += 1024) {
        int i = start + (int)threadIdx.x;
        int v = (i < n) ? g_deg[i] : 0;
        __syncthreads();
        buf[threadIdx.x] = v;
        __syncthreads();
        #pragma unroll
        for (int o = 1; o < 1024; o <<= 1) {
            int t = (threadIdx.x >= (unsigned)o) ? buf[threadIdx.x - o] : 0;
            __syncthreads();
            buf[threadIdx.x] += t;
            __syncthreads();
        }
        int incl  = buf[threadIdx.x];
        int total = buf[1023];
        if (i < n) {
            int ex = base + incl - v;
            g_off[i] = ex;
            g_cur[i] = ex;
        }
        base += total;
    }
}
__global__ void scatter_k(const int* __restrict__ src, const int* __restrict__ dst, int E) {
    int i = blockIdx.x * blockDim.x + threadIdx.x;
    if (i < E) {
        int p = atomicAdd(&g_cur[dst[i]], 1);
        g_esrc[p] = src[i];
    }
}

// ---------------- segment mean ----------------
// HALF=true: write fp16 (for tensor GEMM); HALF=false: write fp32 (for final layer)
template <int F, bool HALF>
__global__ void aggregate_k(const float* __restrict__ feat, void* __restrict__ outp) {
    int v = blockIdx.x;
    int t = threadIdx.x;
    int o = g_off[v];
    int d = g_deg[v];
    float4 acc = make_float4(0.f, 0.f, 0.f, 0.f);
    for (int j = 0; j < d; j++) {
        int s = g_esrc[o + j];
        float4 x = *reinterpret_cast<const float4*>(&feat[(size_t)s * F + t * 4]);
        acc.x += x.x; acc.y += x.y; acc.z += x.z; acc.w += x.w;
    }
    float inv = 1.0f / (float)max(d, 1);
    acc.x *= inv; acc.y *= inv; acc.z *= inv; acc.w *= inv;
    if (HALF) {
        __half2* out = reinterpret_cast<__half2*>(outp);
        size_t base = ((size_t)v * F + t * 4) / 2;
        out[base]     = __floats2half2_rn(acc.x, acc.y);
        out[base + 1] = __floats2half2_rn(acc.z, acc.w);
    } else {
        float* out = reinterpret_cast<float*>(outp);
        *reinterpret_cast<float4*>(&out[(size_t)v * F + t * 4]) = acc;
    }
}

// ---------------- fp32 -> fp16 copy ----------------
__global__ void cvt_half_k(const float* __restrict__ in, __half* __restrict__ out, int n4) {
    int i = blockIdx.x * blockDim.x + threadIdx.x;
    if (i < n4) {
        float4 v = reinterpret_cast<const float4*>(in)[i];
        __half2* o = reinterpret_cast<__half2*>(out) + 2 * i;
        o[0] = __floats2half2_rn(v.x, v.y);
        o[1] = __floats2half2_rn(v.z, v.w);
    }
}

// ---------------- weight transpose + fp16: W[K,N] -> Wt[N,K] ----------------
__global__ void transpose_cvt_k(const float* __restrict__ W, __half* __restrict__ Wt,
                                int K, int N) {
    __shared__ float tile[32][33];
    int n0 = blockIdx.x * 32, k0 = blockIdx.y * 32;
    tile[threadIdx.y][threadIdx.x] = W[(size_t)(k0 + threadIdx.y) * N + n0 + threadIdx.x];
    __syncthreads();
    Wt[(size_t)(n0 + threadIdx.y) * K + k0 + threadIdx.x] = __float2half_rn(tile[threadIdx.x][threadIdx.y]);
}

// ---------------- fp16 mma.sync dual GEMM ----------------
// C[M,N] = act(A1@W1 + A2@W2 + bias); A,B fp16, fp32 accumulate.
// A row-major [M,K], B [N,K] K-major. 128x128 CTA tile, BK=32, 256 threads
// (2x4 warps, 64x32 warp tile), 2-stage cp.async. M%128==0, N%128==0, K%32==0.
// Optional: rows < M2 also stored fp16 to C2h.
static constexpr int SH       = 40;                // halves per 32-col row (80B pitch)
static constexpr int ATILE_H  = 128 * SH;          // 5120 halves
static constexpr int STAGE_H  = 2 * ATILE_H;       // A + B
static constexpr int SM_BYTES = 2 * STAGE_H * 2;   // 40960 bytes

template <bool RELU>
__global__ __launch_bounds__(256)
void gemm_mma_k(const __half* __restrict__ A1, const __half* __restrict__ A2,
                const __half* __restrict__ B1t, const __half* __restrict__ B2t,
                const float* __restrict__ bias, float* __restrict__ C,
                __half* __restrict__ C2h, int M2,
                int M, int N, int K) {
    extern __shared__ __half smh[];
    const uint32_t sbase = smem_to_u32(smh);
    const int tid  = threadIdx.x;
    const int wid  = tid >> 5;
    const int lane = tid & 31;
    const int wm   = wid >> 2;        // 0..1
    const int wn   = wid & 3;         // 0..3
    const int g    = lane >> 2;       // 0..7
    const int tig  = lane & 3;        // 0..3
    const int bm   = blockIdx.y * 128;
    const int bn   = blockIdx.x * 128;

    const int ldrow = tid >> 2;       // 0..63 (and +64)
    const int ldseg = tid & 3;        // 16B segment (8 halves)

    float acc[4][4][4];
    #pragma unroll
    for (int mt = 0; mt < 4; mt++)
        #pragma unroll
        for (int nt = 0; nt < 4; nt++)
            #pragma unroll
            for (int i = 0; i < 4; i++) acc[mt][nt][i] = 0.f;

    const int kt = K / 32;
    const int T  = 2 * kt;

    auto issue_load = [&](int t, int s) {
        int pass = t >= kt;
        int k0 = (t - pass * kt) * 32;
        const __half* __restrict__ A = pass ? A2 : A1;
        const __half* __restrict__ B = pass ? B2t : B1t;
        uint32_t abase = sbase + (uint32_t)(s * STAGE_H) * 2;
        uint32_t bbase = abase + (uint32_t)ATILE_H * 2;
        #pragma unroll
        for (int i = 0; i < 2; i++) {
            int row = ldrow + i * 64;
            uint32_t off = (uint32_t)(row * SH + ldseg * 8) * 2;
            cp_async16(abase + off, &A[(size_t)(bm + row) * K + k0 + ldseg * 8]);
            cp_async16(bbase + off, &B[(size_t)(bn + row) * K + k0 + ldseg * 8]);
        }
        cp_commit();
    };

    issue_load(0, 0);

    for (int t = 0; t < T; t++) {
        int s = t & 1;
        if (t + 1 < T) { issue_load(t + 1, s ^ 1); cp_wait<1>(); }
        else           { cp_wait<0>(); }
        __syncthreads();

        const __half* As = smh + s * STAGE_H;
        const __half* Bs = As + ATILE_H;
        #pragma unroll
        for (int ks = 0; ks < 2; ks++) {
            const int kb = ks * 16;
            uint32_t a[4][4], b[4][2];
            #pragma unroll
            for (int mt = 0; mt < 4; mt++) {
                int rb = wm * 64 + mt * 16 + g;
                a[mt][0] = *reinterpret_cast<const uint32_t*>(As + (rb    ) * SH + kb + 2 * tig);
                a[mt][1] = *reinterpret_cast<const uint32_t*>(As + (rb + 8) * SH + kb + 2 * tig);
                a[mt][2] = *reinterpret_cast<const uint32_t*>(As + (rb    ) * SH + kb + 2 * tig + 8);
                a[mt][3] = *reinterpret_cast<const uint32_t*>(As + (rb + 8) * SH + kb + 2 * tig + 8);
            }
            #pragma unroll
            for (int nt = 0; nt < 4; nt++) {
                int nb = wn * 32 + nt * 8 + g;
                b[nt][0] = *reinterpret_cast<const uint32_t*>(Bs + nb * SH + kb + 2 * tig);
                b[nt][1] = *reinterpret_cast<const uint32_t*>(Bs + nb * SH + kb + 2 * tig + 8);
            }
            #pragma unroll
            for (int mt = 0; mt < 4; mt++)
                #pragma unroll
                for (int nt = 0; nt < 4; nt++)
                    mma_f16(acc[mt][nt], a[mt], b[nt]);
        }
        __syncthreads();   // reads of stage s done before next issue overwrites it
    }

    #pragma unroll
    for (int mt = 0; mt < 4; mt++) {
        int r0 = bm + wm * 64 + mt * 16 + g;
        #pragma unroll
        for (int nt = 0; nt < 4; nt++) {
            int c = bn + wn * 32 + nt * 8 + 2 * tig;
            float bx = __ldg(&bias[c]), by = __ldg(&bias[c + 1]);
            float2 v0 = make_float2(acc[mt][nt][0] + bx, acc[mt][nt][1] + by);
            float2 v1 = make_float2(acc[mt][nt][2] + bx, acc[mt][nt][3] + by);
            if (RELU) {
                v0.x = fmaxf(v0.x, 0.f); v0.y = fmaxf(v0.y, 0.f);
                v1.x = fmaxf(v1.x, 0.f); v1.y = fmaxf(v1.y, 0.f);
            }
            *reinterpret_cast<float2*>(&C[(size_t)r0 * N + c]) = v0;
            *reinterpret_cast<float2*>(&C[(size_t)(r0 + 8) * N + c]) = v1;
            if (C2h != nullptr && r0 < M2) {   // M2 % 128 == 0, whole 16-row tile in range
                *reinterpret_cast<__half2*>(&C2h[(size_t)r0 * N + c])       = __floats2half2_rn(v0.x, v0.y);
                *reinterpret_cast<__half2*>(&C2h[(size_t)(r0 + 8) * N + c]) = __floats2half2_rn(v1.x, v1.y);
            }
        }
    }
}

// ---------------- small final GEMM (N=47) ----------------
__global__ void gemm_small_k(const float* __restrict__ A1, const float* __restrict__ A2,
                             const float* __restrict__ B1, const float* __restrict__ B2,
                             const float* __restrict__ bias, float* __restrict__ C,
                             int K, int N) {
    __shared__ float a1[HH];
    __shared__ float a2[HH];
    int m = blockIdx.x;
    for (int i = threadIdx.x; i < K; i += blockDim.x) {
        a1[i] = A1[(size_t)m * K + i];
        a2[i] = A2[(size_t)m * K + i];
    }
    __syncthreads();
    for (int c = threadIdx.x; c < N; c += blockDim.x) {
        float s = bias[c];
        #pragma unroll 8
        for (int k = 0; k < K; k++)
            s += a1[k] * B1[(size_t)k * N + c] + a2[k] * B2[(size_t)k * N + c];
        C[(size_t)m * N + c] = s;
    }
}

// ---------------- launch ----------------
extern "C" void kernel_launch(void* const* d_in, const int* in_sizes, int n_in,
                              void* d_out, int out_size) {
    const float* x   = (const float*)d_in[0];
    const int* src0  = (const int*)d_in[1];
    const int* dst0  = (const int*)d_in[2];
    const int* src1  = (const int*)d_in[3];
    const int* dst1  = (const int*)d_in[4];
    const int* src2  = (const int*)d_in[5];
    const int* dst2  = (const int*)d_in[6];
    const float* Ws0 = (const float*)d_in[7];
    const float* Wn0 = (const float*)d_in[8];
    const float* b0  = (const float*)d_in[9];
    const float* Ws1 = (const float*)d_in[10];
    const float* Wn1 = (const float*)d_in[11];
    const float* b1  = (const float*)d_in[12];
    const float* Ws2 = (const float*)d_in[13];
    const float* Wn2 = (const float*)d_in[14];
    const float* b2  = (const float*)d_in[15];
    float* out = (float*)d_out;

    float  *h1_p, *h2_p, *m_p;
    __half *mh_p, *xh_p, *h1h_p, *w0t_p, *w1t_p;
    cudaGetSymbolAddress((void**)&h1_p, g_h1);
    cudaGetSymbolAddress((void**)&h2_p, g_h2);
    cudaGetSymbolAddress((void**)&m_p, g_mean);
    cudaGetSymbolAddress((void**)&mh_p, g_meanh);
    cudaGetSymbolAddress((void**)&xh_p, g_xh);
    cudaGetSymbolAddress((void**)&h1h_p, g_h1h);
    cudaGetSymbolAddress((void**)&w0t_p, g_W0t);
    cudaGetSymbolAddress((void**)&w1t_p, g_W1t);

    static int inited = 0;
    if (!inited) {
        cudaFuncSetAttribute(gemm_mma_k<true>,
                             cudaFuncAttributeMaxDynamicSharedMemorySize, SM_BYTES);
        cudaFuncSetAttribute(gemm_mma_k<false>,
                             cudaFuncAttributeMaxDynamicSharedMemorySize, SM_BYTES);
        inited = 1;
    }

    // ---- weight prep + x-prefix fp16 ----
    {
        dim3 blk(32, 32);
        transpose_cvt_k<<<dim3(HH / 32, FF0 / 32), blk>>>(Ws0, w0t_p, FF0, HH);
        transpose_cvt_k<<<dim3(HH / 32, FF0 / 32), blk>>>(Wn0, w0t_p + HH * FF0, FF0, HH);
        transpose_cvt_k<<<dim3(HH / 32, HH / 32), blk>>>(Ws1, w1t_p, HH, HH);
        transpose_cvt_k<<<dim3(HH / 32, HH / 32), blk>>>(Wn1, w1t_p + HH * HH, HH, HH);
        int n4 = NN1 * FF0 / 4;
        cvt_half_k<<<(n4 + 255) / 256, 256>>>(x, xh_p, n4);
    }

    // ---- Layer 0: x[N0,256] -> h1[N1,1024], ReLU; emits fp16 h1 prefix too ----
    zero_deg_k<<<(NN1 + 255) / 256, 256>>>(NN1);
    count_deg_k<<<(EE0 + 255) / 256, 256>>>(dst0, EE0);
    exscan_k<<<1, 1024>>>(NN1);
    scatter_k<<<(EE0 + 255) / 256, 256>>>(src0, dst0, EE0);
    aggregate_k<FF0, true><<<NN1, FF0 / 4>>>(x, mh_p);
    gemm_mma_k<true><<<dim3(HH / 128, NN1 / 128), 256, SM_BYTES>>>(
        xh_p, mh_p, w0t_p, w0t_p + HH * FF0, b0, h1_p, h1h_p, NN2, NN1, HH, FF0);

    // ---- Layer 1: h1[N1,1024] -> h2[N2,1024], ReLU ----
    zero_deg_k<<<(NN2 + 255) / 256, 256>>>(NN2);
    count_deg_k<<<(EE1 + 255) / 256, 256>>>(dst1, EE1);
    exscan_k<<<1, 1024>>>(NN2);
    scatter_k<<<(EE1 + 255) / 256, 256>>>(src1, dst1, EE1);
    aggregate_k<HH, true><<<NN2, HH / 4>>>(h1_p, mh_p);
    gemm_mma_k<true><<<dim3(HH / 128, NN2 / 128), 256, SM_BYTES>>>(
        h1h_p, mh_p, w1t_p, w1t_p + HH * HH, b1, h2_p, (__half*)nullptr, 0, NN2, HH, HH);

    // ---- Layer 2: h2[N2,1024] -> out[N3,47], no activation (fp32 SIMT) ----
    zero_deg_k<<<(NN3 + 255) / 256, 256>>>(NN3);
    count_deg_k<<<(EE2 + 255) / 256, 256>>>(dst2, EE2);
    exscan_k<<<1, 1024>>>(NN3);
    scatter_k<<<(EE2 + 255) / 256, 256>>>(src2, dst2, EE2);
    aggregate_k<HH, false><<<NN3, HH / 4>>>(h2_p, m_p);
    gemm_small_k<<<NN3, 128>>>(h2_p, m_p, Ws2, Wn2, b2, out, HH, CC);
}

// round 16
// speedup vs baseline: 1.6587x; 1.0530x over previous
#include <cuda_runtime.h>
#include <cuda_fp16.h>
#include <cstdint>

// ---------------- problem constants ----------------
#define NN0 540672
#define NN1 33792
#define NN2 3072
#define NN3 512
#define EE0 506880
#define EE1 30720
#define EE2 2560
#define FF0 256
#define HH  1024
#define CC  47

// ---------------- device scratch (no allocations allowed) ----------------
__device__ float  g_h2[(size_t)NN2 * HH];   // layer-1 output (fp32, for L2)
__device__ float  g_mean[NN3 * HH];         // fp32 mean for layer 2
__device__ __half g_meanh[NN1 * FF0];       // fp16 mean (L0: NN1*256; L1 reuse: NN2*1024)
__device__ __half g_xh[NN1 * FF0];          // fp16 x prefix
__device__ __half g_h1h[(size_t)NN1 * HH];  // fp16 layer-0 output (full)
__device__ int    g_deg[NN1];
__device__ int    g_off[NN1];
__device__ int    g_cur[NN1];
__device__ int    g_esrc[EE0];
// transposed fp16 weights, [N][K] K-major
__device__ __half g_W0t[2 * HH * FF0];
__device__ __half g_W1t[2 * HH * HH];

// ---------------- helpers ----------------
__device__ __forceinline__ uint32_t smem_to_u32(const void* p) {
    uint32_t a;
    asm("{ .reg .u64 t; cvta.to.shared.u64 t, %1; cvt.u32.u64 %0, t; }" : "=r"(a) : "l"(p));
    return a;
}
__device__ __forceinline__ void cp_async16(uint32_t saddr, const void* gaddr) {
    asm volatile("cp.async.ca.shared.global [%0], [%1], 16;" :: "r"(saddr), "l"(gaddr) : "memory");
}
__device__ __forceinline__ void cp_commit() {
    asm volatile("cp.async.commit_group;" ::: "memory");
}
template <int N>
__device__ __forceinline__ void cp_wait() {
    asm volatile("cp.async.wait_group %0;" :: "n"(N) : "memory");
}
__device__ __forceinline__ void ldmatrix_x4(uint32_t& r0, uint32_t& r1, uint32_t& r2, uint32_t& r3,
                                            uint32_t addr) {
    asm volatile("ldmatrix.sync.aligned.m8n8.x4.shared.b16 {%0,%1,%2,%3}, [%4];"
                 : "=r"(r0), "=r"(r1), "=r"(r2), "=r"(r3) : "r"(addr));
}
// m16n8k16 fp16 MMA, fp32 accumulate
__device__ __forceinline__ void mma_f16(float* c, const uint32_t* a, const uint32_t* b) {
    asm volatile(
        "mma.sync.aligned.m16n8k16.row.col.f32.f16.f16.f32 "
        "{%0,%1,%2,%3}, {%4,%5,%6,%7}, {%8,%9}, {%0,%1,%2,%3};"
        : "+f"(c[0]), "+f"(c[1]), "+f"(c[2]), "+f"(c[3])
        : "r"(a[0]), "r"(a[1]), "r"(a[2]), "r"(a[3]), "r"(b[0]), "r"(b[1]));
}

// ---------------- CSR build ----------------
__global__ void zero_deg_k(int n) {
    int i = blockIdx.x * blockDim.x + threadIdx.x;
    if (i < n) g_deg[i] = 0;
}
__global__ void count_deg_k(const int* __restrict__ dst, int E) {
    int i = blockIdx.x * blockDim.x + threadIdx.x;
    if (i < E) atomicAdd(&g_deg[dst[i]], 1);
}
__global__ void exscan_k(int n) {
    __shared__ int buf[1024];
    int base = 0;
    for (int start = 0; start < n; start += 1024) {
        int i = start + (int)threadIdx.x;
        int v = (i < n) ? g_deg[i] : 0;
        __syncthreads();
        buf[threadIdx.x] = v;
        __syncthreads();
        #pragma unroll
        for (int o = 1; o < 1024; o <<= 1) {
            int t = (threadIdx.x >= (unsigned)o) ? buf[threadIdx.x - o] : 0;
            __syncthreads();
            buf[threadIdx.x] += t;
            __syncthreads();
        }
        int incl  = buf[threadIdx.x];
        int total = buf[1023];
        if (i < n) {
            int ex = base + incl - v;
            g_off[i] = ex;
            g_cur[i] = ex;
        }
        base += total;
    }
}
__global__ void scatter_k(const int* __restrict__ src, const int* __restrict__ dst, int E) {
    int i = blockIdx.x * blockDim.x + threadIdx.x;
    if (i < E) {
        int p = atomicAdd(&g_cur[dst[i]], 1);
        g_esrc[p] = src[i];
    }
}

// ---------------- segment mean: fp32 in -> fp16 or fp32 out ----------------
template <int F, bool HALF>
__global__ void aggregate_k(const float* __restrict__ feat, void* __restrict__ outp) {
    int v = blockIdx.x;
    int t = threadIdx.x;
    int o = g_off[v];
    int d = g_deg[v];
    float4 acc = make_float4(0.f, 0.f, 0.f, 0.f);
    for (int j = 0; j < d; j++) {
        int s = g_esrc[o + j];
        float4 x = *reinterpret_cast<const float4*>(&feat[(size_t)s * F + t * 4]);
        acc.x += x.x; acc.y += x.y; acc.z += x.z; acc.w += x.w;
    }
    float inv = 1.0f / (float)max(d, 1);
    acc.x *= inv; acc.y *= inv; acc.z *= inv; acc.w *= inv;
    if (HALF) {
        __half2* out = reinterpret_cast<__half2*>(outp);
        size_t base = ((size_t)v * F + t * 4) / 2;
        out[base]     = __floats2half2_rn(acc.x, acc.y);
        out[base + 1] = __floats2half2_rn(acc.z, acc.w);
    } else {
        float* out = reinterpret_cast<float*>(outp);
        *reinterpret_cast<float4*>(&out[(size_t)v * F + t * 4]) = acc;
    }
}

// ---------------- segment mean: fp16 in -> fp16 out ----------------
template <int F>
__global__ void aggregate_h_k(const __half* __restrict__ feat, __half* __restrict__ outp) {
    int v = blockIdx.x;
    int t = threadIdx.x;                   // F/4 threads, 4 halves each
    int o = g_off[v];
    int d = g_deg[v];
    float4 acc = make_float4(0.f, 0.f, 0.f, 0.f);
    for (int j = 0; j < d; j++) {
        int s = g_esrc[o + j];
        const __half2* p = reinterpret_cast<const __half2*>(&feat[(size_t)s * F + t * 4]);
        float2 x0 = __half22float2(p[0]);
        float2 x1 = __half22float2(p[1]);
        acc.x += x0.x; acc.y += x0.y; acc.z += x1.x; acc.w += x1.y;
    }
    float inv = 1.0f / (float)max(d, 1);
    __half2* out = reinterpret_cast<__half2*>(&outp[(size_t)v * F + t * 4]);
    out[0] = __floats2half2_rn(acc.x * inv, acc.y * inv);
    out[1] = __floats2half2_rn(acc.z * inv, acc.w * inv);
}

// ---------------- fp32 -> fp16 copy ----------------
__global__ void cvt_half_k(const float* __restrict__ in, __half* __restrict__ out, int n4) {
    int i = blockIdx.x * blockDim.x + threadIdx.x;
    if (i < n4) {
        float4 v = reinterpret_cast<const float4*>(in)[i];
        __half2* o = reinterpret_cast<__half2*>(out) + 2 * i;
        o[0] = __floats2half2_rn(v.x, v.y);
        o[1] = __floats2half2_rn(v.z, v.w);
    }
}

// ---------------- weight transpose + fp16: W[K,N] -> Wt[N,K] ----------------
__global__ void transpose_cvt_k(const float* __restrict__ W, __half* __restrict__ Wt,
                                int K, int N) {
    __shared__ float tile[32][33];
    int n0 = blockIdx.x * 32, k0 = blockIdx.y * 32;
    tile[threadIdx.y][threadIdx.x] = W[(size_t)(k0 + threadIdx.y) * N + n0 + threadIdx.x];
    __syncthreads();
    Wt[(size_t)(n0 + threadIdx.y) * K + k0 + threadIdx.x] = __float2half_rn(tile[threadIdx.x][threadIdx.y]);
}

// ---------------- fp16 mma.sync dual GEMM ----------------
// C[M,N] = act(A1@W1 + A2@W2 + bias); fp16 operands, fp32 accumulate.
// 128x128 CTA tile, BK=32, 256 threads (2x4 warps, 64x32 warp tile),
// 3-stage cp.async pipeline, single __syncthreads per tile, ldmatrix fragments.
// M%128==0, N%128==0, K%32==0. OUTHALF: C is __half* else float*.
static constexpr int SH       = 40;                // halves per 32-col row (80B pitch)
static constexpr int ATILE_H  = 128 * SH;          // 5120 halves
static constexpr int STAGE_H  = 2 * ATILE_H;       // A + B per stage
static constexpr int NSTAGE   = 3;
static constexpr int SM_BYTES = NSTAGE * STAGE_H * 2;  // 61440 bytes

template <bool RELU, bool OUTHALF>
__global__ __launch_bounds__(256)
void gemm_mma_k(const __half* __restrict__ A1, const __half* __restrict__ A2,
                const __half* __restrict__ B1t, const __half* __restrict__ B2t,
                const float* __restrict__ bias, void* __restrict__ Cp,
                int M, int N, int K) {
    extern __shared__ __half smh[];
    const uint32_t sbase = smem_to_u32(smh);
    const int tid  = threadIdx.x;
    const int wid  = tid >> 5;
    const int lane = tid & 31;
    const int wm   = wid >> 2;        // 0..1
    const int wn   = wid & 3;         // 0..3
    const int g    = lane >> 2;       // 0..7
    const int tig  = lane & 3;        // 0..3
    const int bm   = blockIdx.y * 128;
    const int bn   = blockIdx.x * 128;

    const int ldrow = tid >> 2;       // 0..63 (and +64)
    const int ldseg = tid & 3;        // 16B segment (8 halves)

    // ldmatrix per-lane offsets
    const int arow = (lane & 7) + 8 * ((lane >> 3) & 1);
    const int acol = 8 * (lane >> 4);
    const int brow = (lane & 7) + 8 * (lane >> 4);
    const int bcol = 8 * ((lane >> 3) & 1);

    float acc[4][4][4];
    #pragma unroll
    for (int mt = 0; mt < 4; mt++)
        #pragma unroll
        for (int nt = 0; nt < 4; nt++)
            #pragma unroll
            for (int i = 0; i < 4; i++) acc[mt][nt][i] = 0.f;

    const int kt = K / 32;
    const int T  = 2 * kt;

    auto issue_load = [&](int t) {
        int s = t % NSTAGE;
        int pass = t >= kt;
        int k0 = (t - pass * kt) * 32;
        const __half* __restrict__ A = pass ? A2 : A1;
        const __half* __restrict__ B = pass ? B2t : B1t;
        uint32_t abase = sbase + (uint32_t)(s * STAGE_H) * 2;
        uint32_t bbase = abase + (uint32_t)ATILE_H * 2;
        #pragma unroll
        for (int i = 0; i < 2; i++) {
            int row = ldrow + i * 64;
            uint32_t off = (uint32_t)(row * SH + ldseg * 8) * 2;
            cp_async16(abase + off, &A[(size_t)(bm + row) * K + k0 + ldseg * 8]);
            cp_async16(bbase + off, &B[(size_t)(bn + row) * K + k0 + ldseg * 8]);
        }
        cp_commit();
    };

    issue_load(0);
    issue_load(1);

    for (int t = 0; t < T; t++) {
        cp_wait<1>();
        __syncthreads();            // stage t ready; all warps done computing t-1
        if (t + 2 < T) issue_load(t + 2);   // fills slot (t-1)%3, freed by the barrier
        else           cp_commit();          // keep wait-group accounting exact

        int s = t % NSTAGE;
        uint32_t As_addr = sbase + (uint32_t)(s * STAGE_H) * 2;
        uint32_t Bs_addr = As_addr + (uint32_t)ATILE_H * 2;

        #pragma unroll
        for (int ks = 0; ks < 2; ks++) {
            const int kb = ks * 16;
            uint32_t a[4][4], b[4][2];
            #pragma unroll
            for (int mt = 0; mt < 4; mt++) {
                uint32_t addr = As_addr +
                    (uint32_t)((wm * 64 + mt * 16 + arow) * SH + kb + acol) * 2;
                ldmatrix_x4(a[mt][0], a[mt][1], a[mt][2], a[mt][3], addr);
            }
            #pragma unroll
            for (int p = 0; p < 2; p++) {
                uint32_t addr = Bs_addr +
                    (uint32_t)((wn * 32 + p * 16 + brow) * SH + kb + bcol) * 2;
                ldmatrix_x4(b[2*p][0], b[2*p][1], b[2*p+1][0], b[2*p+1][1], addr);
            }
            #pragma unroll
            for (int mt = 0; mt < 4; mt++)
                #pragma unroll
                for (int nt = 0; nt < 4; nt++)
                    mma_f16(acc[mt][nt], a[mt], b[nt]);
        }
    }

    #pragma unroll
    for (int mt = 0; mt < 4; mt++) {
        int r0 = bm + wm * 64 + mt * 16 + g;
        #pragma unroll
        for (int nt = 0; nt < 4; nt++) {
            int c = bn + wn * 32 + nt * 8 + 2 * tig;
            float bx = __ldg(&bias[c]), by = __ldg(&bias[c + 1]);
            float2 v0 = make_float2(acc[mt][nt][0] + bx, acc[mt][nt][1] + by);
            float2 v1 = make_float2(acc[mt][nt][2] + bx, acc[mt][nt][3] + by);
            if (RELU) {
                v0.x = fmaxf(v0.x, 0.f); v0.y = fmaxf(v0.y, 0.f);
                v1.x = fmaxf(v1.x, 0.f); v1.y = fmaxf(v1.y, 0.f);
            }
            if (OUTHALF) {
                __half* C = reinterpret_cast<__half*>(Cp);
                *reinterpret_cast<__half2*>(&C[(size_t)r0 * N + c])       = __floats2half2_rn(v0.x, v0.y);
                *reinterpret_cast<__half2*>(&C[(size_t)(r0 + 8) * N + c]) = __floats2half2_rn(v1.x, v1.y);
            } else {
                float* C = reinterpret_cast<float*>(Cp);
                *reinterpret_cast<float2*>(&C[(size_t)r0 * N + c]) = v0;
                *reinterpret_cast<float2*>(&C[(size_t)(r0 + 8) * N + c]) = v1;
            }
        }
    }
}

// ---------------- small final GEMM (N=47) ----------------
__global__ void gemm_small_k(const float* __restrict__ A1, const float* __restrict__ A2,
                             const float* __restrict__ B1, const float* __restrict__ B2,
                             const float* __restrict__ bias, float* __restrict__ C,
                             int K, int N) {
    __shared__ float a1[HH];
    __shared__ float a2[HH];
    int m = blockIdx.x;
    for (int i = threadIdx.x; i < K; i += blockDim.x) {
        a1[i] = A1[(size_t)m * K + i];
        a2[i] = A2[(size_t)m * K + i];
    }
    __syncthreads();
    for (int c = threadIdx.x; c < N; c += blockDim.x) {
        float s = bias[c];
        #pragma unroll 8
        for (int k = 0; k < K; k++)
            s += a1[k] * B1[(size_t)k * N + c] + a2[k] * B2[(size_t)k * N + c];
        C[(size_t)m * N + c] = s;
    }
}

// ---------------- launch ----------------
extern "C" void kernel_launch(void* const* d_in, const int* in_sizes, int n_in,
                              void* d_out, int out_size) {
    const float* x   = (const float*)d_in[0];
    const int* src0  = (const int*)d_in[1];
    const int* dst0  = (const int*)d_in[2];
    const int* src1  = (const int*)d_in[3];
    const int* dst1  = (const int*)d_in[4];
    const int* src2  = (const int*)d_in[5];
    const int* dst2  = (const int*)d_in[6];
    const float* Ws0 = (const float*)d_in[7];
    const float* Wn0 = (const float*)d_in[8];
    const float* b0  = (const float*)d_in[9];
    const float* Ws1 = (const float*)d_in[10];
    const float* Wn1 = (const float*)d_in[11];
    const float* b1  = (const float*)d_in[12];
    const float* Ws2 = (const float*)d_in[13];
    const float* Wn2 = (const float*)d_in[14];
    const float* b2  = (const float*)d_in[15];
    float* out = (float*)d_out;

    float  *h2_p, *m_p;
    __half *mh_p, *xh_p, *h1h_p, *w0t_p, *w1t_p;
    cudaGetSymbolAddress((void**)&h2_p, g_h2);
    cudaGetSymbolAddress((void**)&m_p, g_mean);
    cudaGetSymbolAddress((void**)&mh_p, g_meanh);
    cudaGetSymbolAddress((void**)&xh_p, g_xh);
    cudaGetSymbolAddress((void**)&h1h_p, g_h1h);
    cudaGetSymbolAddress((void**)&w0t_p, g_W0t);
    cudaGetSymbolAddress((void**)&w1t_p, g_W1t);

    static int inited = 0;
    if (!inited) {
        cudaFuncSetAttribute(gemm_mma_k<true, true>,
                             cudaFuncAttributeMaxDynamicSharedMemorySize, SM_BYTES);
        cudaFuncSetAttribute(gemm_mma_k<true, false>,
                             cudaFuncAttributeMaxDynamicSharedMemorySize, SM_BYTES);
        inited = 1;
    }

    // ---- weight prep + x-prefix fp16 ----
    {
        dim3 blk(32, 32);
        transpose_cvt_k<<<dim3(HH / 32, FF0 / 32), blk>>>(Ws0, w0t_p, FF0, HH);
        transpose_cvt_k<<<dim3(HH / 32, FF0 / 32), blk>>>(Wn0, w0t_p + HH * FF0, FF0, HH);
        transpose_cvt_k<<<dim3(HH / 32, HH / 32), blk>>>(Ws1, w1t_p, HH, HH);
        transpose_cvt_k<<<dim3(HH / 32, HH / 32), blk>>>(Wn1, w1t_p + HH * HH, HH, HH);
        int n4 = NN1 * FF0 / 4;
        cvt_half_k<<<(n4 + 255) / 256, 256>>>(x, xh_p, n4);
    }

    // ---- Layer 0: x[N0,256] -> h1h[N1,1024] (fp16), ReLU ----
    zero_deg_k<<<(NN1 + 255) / 256, 256>>>(NN1);
    count_deg_k<<<(EE0 + 255) / 256, 256>>>(dst0, EE0);
    exscan_k<<<1, 1024>>>(NN1);
    scatter_k<<<(EE0 + 255) / 256, 256>>>(src0, dst0, EE0);
    aggregate_k<FF0, true><<<NN1, FF0 / 4>>>(x, mh_p);
    gemm_mma_k<true, true><<<dim3(HH / 128, NN1 / 128), 256, SM_BYTES>>>(
        xh_p, mh_p, w0t_p, w0t_p + HH * FF0, b0, h1h_p, NN1, HH, FF0);

    // ---- Layer 1: h1h[N1,1024] -> h2[N2,1024] (fp32), ReLU ----
    zero_deg_k<<<(NN2 + 255) / 256, 256>>>(NN2);
    count_deg_k<<<(EE1 + 255) / 256, 256>>>(dst1, EE1);
    exscan_k<<<1, 1024>>>(NN2);
    scatter_k<<<(EE1 + 255) / 256, 256>>>(src1, dst1, EE1);
    aggregate_h_k<HH><<<NN2, HH / 4>>>(h1h_p, mh_p);
    gemm_mma_k<true, false><<<dim3(HH / 128, NN2 / 128), 256, SM_BYTES>>>(
        h1h_p, mh_p, w1t_p, w1t_p + HH * HH, b1, h2_p, NN2, HH, HH);

    // ---- Layer 2: h2[N2,1024] -> out[N3,47], no activation (fp32 SIMT) ----
    zero_deg_k<<<(NN3 + 255) / 256, 256>>>(NN3);
    count_deg_k<<<(EE2 + 255) / 256, 256>>>(dst2, EE2);
    exscan_k<<<1, 1024>>>(NN3);
    scatter_k<<<(EE2 + 255) / 256, 256>>>(src2, dst2, EE2);
    aggregate_k<HH, false><<<NN3, HH / 4>>>(h2_p, m_p);
    gemm_small_k<<<NN3, 128>>>(h2_p, m_p, Ws2, Wn2, b2, out, HH, CC);
}

// round 17
// speedup vs baseline: 1.7517x; 1.0560x over previous
#include <cuda_runtime.h>
#include <cuda_fp16.h>
#include <cstdint>

// ---------------- problem constants ----------------
#define NN0 540672
#define NN1 33792
#define NN2 3072
#define NN3 512
#define EE0 506880
#define EE1 30720
#define EE2 2560
#define FF0 256
#define HH  1024
#define CC  47

// ---------------- device scratch (no allocations allowed) ----------------
__device__ float  g_h2[(size_t)NN2 * HH];   // layer-1 output (fp32, for L2)
__device__ float  g_mean[NN3 * HH];         // fp32 mean for layer 2
__device__ __half g_meanh[NN1 * FF0];       // fp16 mean (L0: NN1*256; L1 reuse: NN2*1024)
__device__ __half g_xh[NN1 * FF0];          // fp16 x prefix
__device__ __half g_h1h[(size_t)NN1 * HH];  // fp16 layer-0 output (full)
// per-layer CSR scratch (separate so builds can overlap)
__device__ int g_deg0[NN1], g_off0[NN1], g_cur0[NN1], g_esrc0[EE0];
__device__ int g_deg1[NN2], g_off1[NN2], g_cur1[NN2], g_esrc1[EE1];
__device__ int g_deg2[NN3], g_off2[NN3], g_cur2[NN3], g_esrc2[EE2];
// transposed fp16 weights, [N][K] K-major
__device__ __half g_W0t[2 * HH * FF0];
__device__ __half g_W1t[2 * HH * HH];

// ---------------- helpers ----------------
__device__ __forceinline__ uint32_t smem_to_u32(const void* p) {
    uint32_t a;
    asm("{ .reg .u64 t; cvta.to.shared.u64 t, %1; cvt.u32.u64 %0, t; }" : "=r"(a) : "l"(p));
    return a;
}
__device__ __forceinline__ void cp_async16(uint32_t saddr, const void* gaddr) {
    asm volatile("cp.async.ca.shared.global [%0], [%1], 16;" :: "r"(saddr), "l"(gaddr) : "memory");
}
__device__ __forceinline__ void cp_commit() {
    asm volatile("cp.async.commit_group;" ::: "memory");
}
template <int N>
__device__ __forceinline__ void cp_wait() {
    asm volatile("cp.async.wait_group %0;" :: "n"(N) : "memory");
}
__device__ __forceinline__ void ldmatrix_x4(uint32_t& r0, uint32_t& r1, uint32_t& r2, uint32_t& r3,
                                            uint32_t addr) {
    asm volatile("ldmatrix.sync.aligned.m8n8.x4.shared.b16 {%0,%1,%2,%3}, [%4];"
                 : "=r"(r0), "=r"(r1), "=r"(r2), "=r"(r3) : "r"(addr));
}
__device__ __forceinline__ void mma_f16(float* c, const uint32_t* a, const uint32_t* b) {
    asm volatile(
        "mma.sync.aligned.m16n8k16.row.col.f32.f16.f16.f32 "
        "{%0,%1,%2,%3}, {%4,%5,%6,%7}, {%8,%9}, {%0,%1,%2,%3};"
        : "+f"(c[0]), "+f"(c[1]), "+f"(c[2]), "+f"(c[3])
        : "r"(a[0]), "r"(a[1]), "r"(a[2]), "r"(a[3]), "r"(b[0]), "r"(b[1]));
}

// ---------------- CSR build (pointer-parameterized) ----------------
__global__ void zero_deg_k(int* __restrict__ deg, int n) {
    int i = blockIdx.x * blockDim.x + threadIdx.x;
    if (i < n) deg[i] = 0;
}
__global__ void count_deg_k(const int* __restrict__ dst, int* __restrict__ deg, int E) {
    int i = blockIdx.x * blockDim.x + threadIdx.x;
    if (i < E) atomicAdd(&deg[dst[i]], 1);
}
__global__ void exscan_k(const int* __restrict__ deg, int* __restrict__ off,
                         int* __restrict__ cur, int n) {
    __shared__ int buf[1024];
    int base = 0;
    for (int start = 0; start < n; start += 1024) {
        int i = start + (int)threadIdx.x;
        int v = (i < n) ? deg[i] : 0;
        __syncthreads();
        buf[threadIdx.x] = v;
        __syncthreads();
        #pragma unroll
        for (int o = 1; o < 1024; o <<= 1) {
            int t = (threadIdx.x >= (unsigned)o) ? buf[threadIdx.x - o] : 0;
            __syncthreads();
            buf[threadIdx.x] += t;
            __syncthreads();
        }
        int incl  = buf[threadIdx.x];
        int total = buf[1023];
        if (i < n) {
            int ex = base + incl - v;
            off[i] = ex;
            cur[i] = ex;
        }
        base += total;
    }
}
__global__ void scatter_k(const int* __restrict__ src, const int* __restrict__ dst,
                          int* __restrict__ cur, int* __restrict__ esrc, int E) {
    int i = blockIdx.x * blockDim.x + threadIdx.x;
    if (i < E) {
        int p = atomicAdd(&cur[dst[i]], 1);
        esrc[p] = src[i];
    }
}

// ---------------- segment mean: fp32 in -> fp16 or fp32 out ----------------
template <int F, bool HALF>
__global__ void aggregate_k(const float* __restrict__ feat,
                            const int* __restrict__ off, const int* __restrict__ deg,
                            const int* __restrict__ esrc, void* __restrict__ outp) {
    int v = blockIdx.x;
    int t = threadIdx.x;
    int o = off[v];
    int d = deg[v];
    float4 acc = make_float4(0.f, 0.f, 0.f, 0.f);
    for (int j = 0; j < d; j++) {
        int s = esrc[o + j];
        float4 x = *reinterpret_cast<const float4*>(&feat[(size_t)s * F + t * 4]);
        acc.x += x.x; acc.y += x.y; acc.z += x.z; acc.w += x.w;
    }
    float inv = 1.0f / (float)max(d, 1);
    acc.x *= inv; acc.y *= inv; acc.z *= inv; acc.w *= inv;
    if (HALF) {
        __half2* out = reinterpret_cast<__half2*>(outp);
        size_t base = ((size_t)v * F + t * 4) / 2;
        out[base]     = __floats2half2_rn(acc.x, acc.y);
        out[base + 1] = __floats2half2_rn(acc.z, acc.w);
    } else {
        float* out = reinterpret_cast<float*>(outp);
        *reinterpret_cast<float4*>(&out[(size_t)v * F + t * 4]) = acc;
    }
}

// ---------------- segment mean: fp16 in -> fp16 out ----------------
template <int F>
__global__ void aggregate_h_k(const __half* __restrict__ feat,
                              const int* __restrict__ off, const int* __restrict__ deg,
                              const int* __restrict__ esrc, __half* __restrict__ outp) {
    int v = blockIdx.x;
    int t = threadIdx.x;                   // F/4 threads, 4 halves each
    int o = off[v];
    int d = deg[v];
    float4 acc = make_float4(0.f, 0.f, 0.f, 0.f);
    for (int j = 0; j < d; j++) {
        int s = esrc[o + j];
        const __half2* p = reinterpret_cast<const __half2*>(&feat[(size_t)s * F + t * 4]);
        float2 x0 = __half22float2(p[0]);
        float2 x1 = __half22float2(p[1]);
        acc.x += x0.x; acc.y += x0.y; acc.z += x1.x; acc.w += x1.y;
    }
    float inv = 1.0f / (float)max(d, 1);
    __half2* out = reinterpret_cast<__half2*>(&outp[(size_t)v * F + t * 4]);
    out[0] = __floats2half2_rn(acc.x * inv, acc.y * inv);
    out[1] = __floats2half2_rn(acc.z * inv, acc.w * inv);
}

// ---------------- fp32 -> fp16 copy ----------------
__global__ void cvt_half_k(const float* __restrict__ in, __half* __restrict__ out, int n4) {
    int i = blockIdx.x * blockDim.x + threadIdx.x;
    if (i < n4) {
        float4 v = reinterpret_cast<const float4*>(in)[i];
        __half2* o = reinterpret_cast<__half2*>(out) + 2 * i;
        o[0] = __floats2half2_rn(v.x, v.y);
        o[1] = __floats2half2_rn(v.z, v.w);
    }
}

// ---------------- weight transpose + fp16: W[K,N] -> Wt[N,K] ----------------
__global__ void transpose_cvt_k(const float* __restrict__ W, __half* __restrict__ Wt,
                                int K, int N) {
    __shared__ float tile[32][33];
    int n0 = blockIdx.x * 32, k0 = blockIdx.y * 32;
    tile[threadIdx.y][threadIdx.x] = W[(size_t)(k0 + threadIdx.y) * N + n0 + threadIdx.x];
    __syncthreads();
    Wt[(size_t)(n0 + threadIdx.y) * K + k0 + threadIdx.x] = __float2half_rn(tile[threadIdx.x][threadIdx.y]);
}

// ---------------- fp16 mma.sync dual GEMM (identical to R16) ----------------
static constexpr int SH       = 40;                // halves per 32-col row (80B pitch)
static constexpr int ATILE_H  = 128 * SH;          // 5120 halves
static constexpr int STAGE_H  = 2 * ATILE_H;       // A + B per stage
static constexpr int NSTAGE   = 3;
static constexpr int SM_BYTES = NSTAGE * STAGE_H * 2;  // 61440 bytes

template <bool RELU, bool OUTHALF>
__global__ __launch_bounds__(256)
void gemm_mma_k(const __half* __restrict__ A1, const __half* __restrict__ A2,
                const __half* __restrict__ B1t, const __half* __restrict__ B2t,
                const float* __restrict__ bias, void* __restrict__ Cp,
                int M, int N, int K) {
    extern __shared__ __half smh[];
    const uint32_t sbase = smem_to_u32(smh);
    const int tid  = threadIdx.x;
    const int wid  = tid >> 5;
    const int lane = tid & 31;
    const int wm   = wid >> 2;
    const int wn   = wid & 3;
    const int g    = lane >> 2;
    const int tig  = lane & 3;
    const int bm   = blockIdx.y * 128;
    const int bn   = blockIdx.x * 128;

    const int ldrow = tid >> 2;
    const int ldseg = tid & 3;

    const int arow = (lane & 7) + 8 * ((lane >> 3) & 1);
    const int acol = 8 * (lane >> 4);
    const int brow = (lane & 7) + 8 * (lane >> 4);
    const int bcol = 8 * ((lane >> 3) & 1);

    float acc[4][4][4];
    #pragma unroll
    for (int mt = 0; mt < 4; mt++)
        #pragma unroll
        for (int nt = 0; nt < 4; nt++)
            #pragma unroll
            for (int i = 0; i < 4; i++) acc[mt][nt][i] = 0.f;

    const int kt = K / 32;
    const int T  = 2 * kt;

    auto issue_load = [&](int t) {
        int s = t % NSTAGE;
        int pass = t >= kt;
        int k0 = (t - pass * kt) * 32;
        const __half* __restrict__ A = pass ? A2 : A1;
        const __half* __restrict__ B = pass ? B2t : B1t;
        uint32_t abase = sbase + (uint32_t)(s * STAGE_H) * 2;
        uint32_t bbase = abase + (uint32_t)ATILE_H * 2;
        #pragma unroll
        for (int i = 0; i < 2; i++) {
            int row = ldrow + i * 64;
            uint32_t off = (uint32_t)(row * SH + ldseg * 8) * 2;
            cp_async16(abase + off, &A[(size_t)(bm + row) * K + k0 + ldseg * 8]);
            cp_async16(bbase + off, &B[(size_t)(bn + row) * K + k0 + ldseg * 8]);
        }
        cp_commit();
    };

    issue_load(0);
    issue_load(1);

    for (int t = 0; t < T; t++) {
        cp_wait<1>();
        __syncthreads();
        if (t + 2 < T) issue_load(t + 2);
        else           cp_commit();

        int s = t % NSTAGE;
        uint32_t As_addr = sbase + (uint32_t)(s * STAGE_H) * 2;
        uint32_t Bs_addr = As_addr + (uint32_t)ATILE_H * 2;

        #pragma unroll
        for (int ks = 0; ks < 2; ks++) {
            const int kb = ks * 16;
            uint32_t a[4][4], b[4][2];
            #pragma unroll
            for (int mt = 0; mt < 4; mt++) {
                uint32_t addr = As_addr +
                    (uint32_t)((wm * 64 + mt * 16 + arow) * SH + kb + acol) * 2;
                ldmatrix_x4(a[mt][0], a[mt][1], a[mt][2], a[mt][3], addr);
            }
            #pragma unroll
            for (int p = 0; p < 2; p++) {
                uint32_t addr = Bs_addr +
                    (uint32_t)((wn * 32 + p * 16 + brow) * SH + kb + bcol) * 2;
                ldmatrix_x4(b[2*p][0], b[2*p][1], b[2*p+1][0], b[2*p+1][1], addr);
            }
            #pragma unroll
            for (int mt = 0; mt < 4; mt++)
                #pragma unroll
                for (int nt = 0; nt < 4; nt++)
                    mma_f16(acc[mt][nt], a[mt], b[nt]);
        }
    }

    #pragma unroll
    for (int mt = 0; mt < 4; mt++) {
        int r0 = bm + wm * 64 + mt * 16 + g;
        #pragma unroll
        for (int nt = 0; nt < 4; nt++) {
            int c = bn + wn * 32 + nt * 8 + 2 * tig;
            float bx = __ldg(&bias[c]), by = __ldg(&bias[c + 1]);
            float2 v0 = make_float2(acc[mt][nt][0] + bx, acc[mt][nt][1] + by);
            float2 v1 = make_float2(acc[mt][nt][2] + bx, acc[mt][nt][3] + by);
            if (RELU) {
                v0.x = fmaxf(v0.x, 0.f); v0.y = fmaxf(v0.y, 0.f);
                v1.x = fmaxf(v1.x, 0.f); v1.y = fmaxf(v1.y, 0.f);
            }
            if (OUTHALF) {
                __half* C = reinterpret_cast<__half*>(Cp);
                *reinterpret_cast<__half2*>(&C[(size_t)r0 * N + c])       = __floats2half2_rn(v0.x, v0.y);
                *reinterpret_cast<__half2*>(&C[(size_t)(r0 + 8) * N + c]) = __floats2half2_rn(v1.x, v1.y);
            } else {
                float* C = reinterpret_cast<float*>(Cp);
                *reinterpret_cast<float2*>(&C[(size_t)r0 * N + c]) = v0;
                *reinterpret_cast<float2*>(&C[(size_t)(r0 + 8) * N + c]) = v1;
            }
        }
    }
}

// ---------------- small final GEMM (N=47) ----------------
__global__ void gemm_small_k(const float* __restrict__ A1, const float* __restrict__ A2,
                             const float* __restrict__ B1, const float* __restrict__ B2,
                             const float* __restrict__ bias, float* __restrict__ C,
                             int K, int N) {
    __shared__ float a1[HH];
    __shared__ float a2[HH];
    int m = blockIdx.x;
    for (int i = threadIdx.x; i < K; i += blockDim.x) {
        a1[i] = A1[(size_t)m * K + i];
        a2[i] = A2[(size_t)m * K + i];
    }
    __syncthreads();
    for (int c = threadIdx.x; c < N; c += blockDim.x) {
        float s = bias[c];
        #pragma unroll 8
        for (int k = 0; k < K; k++)
            s += a1[k] * B1[(size_t)k * N + c] + a2[k] * B2[(size_t)k * N + c];
        C[(size_t)m * N + c] = s;
    }
}

// ---------------- launch ----------------
extern "C" void kernel_launch(void* const* d_in, const int* in_sizes, int n_in,
                              void* d_out, int out_size) {
    const float* x   = (const float*)d_in[0];
    const int* src0  = (const int*)d_in[1];
    const int* dst0  = (const int*)d_in[2];
    const int* src1  = (const int*)d_in[3];
    const int* dst1  = (const int*)d_in[4];
    const int* src2  = (const int*)d_in[5];
    const int* dst2  = (const int*)d_in[6];
    const float* Ws0 = (const float*)d_in[7];
    const float* Wn0 = (const float*)d_in[8];
    const float* b0  = (const float*)d_in[9];
    const float* Ws1 = (const float*)d_in[10];
    const float* Wn1 = (const float*)d_in[11];
    const float* b1  = (const float*)d_in[12];
    const float* Ws2 = (const float*)d_in[13];
    const float* Wn2 = (const float*)d_in[14];
    const float* b2  = (const float*)d_in[15];
    float* out = (float*)d_out;

    float  *h2_p, *m_p;
    __half *mh_p, *xh_p, *h1h_p, *w0t_p, *w1t_p;
    int *deg0, *off0, *cur0, *es0, *deg1, *off1, *cur1, *es1, *deg2, *off2, *cur2, *es2;
    cudaGetSymbolAddress((void**)&h2_p, g_h2);
    cudaGetSymbolAddress((void**)&m_p, g_mean);
    cudaGetSymbolAddress((void**)&mh_p, g_meanh);
    cudaGetSymbolAddress((void**)&xh_p, g_xh);
    cudaGetSymbolAddress((void**)&h1h_p, g_h1h);
    cudaGetSymbolAddress((void**)&w0t_p, g_W0t);
    cudaGetSymbolAddress((void**)&w1t_p, g_W1t);
    cudaGetSymbolAddress((void**)&deg0, g_deg0); cudaGetSymbolAddress((void**)&off0, g_off0);
    cudaGetSymbolAddress((void**)&cur0, g_cur0); cudaGetSymbolAddress((void**)&es0, g_esrc0);
    cudaGetSymbolAddress((void**)&deg1, g_deg1); cudaGetSymbolAddress((void**)&off1, g_off1);
    cudaGetSymbolAddress((void**)&cur1, g_cur1); cudaGetSymbolAddress((void**)&es1, g_esrc1);
    cudaGetSymbolAddress((void**)&deg2, g_deg2); cudaGetSymbolAddress((void**)&off2, g_off2);
    cudaGetSymbolAddress((void**)&cur2, g_cur2); cudaGetSymbolAddress((void**)&es2, g_esrc2);

    static cudaStream_t sW = nullptr, sC = nullptr;
    static cudaEvent_t eIn, eW, eC1, eC2;
    static int inited = 0;
    if (!inited) {
        cudaFuncSetAttribute(gemm_mma_k<true, true>,
                             cudaFuncAttributeMaxDynamicSharedMemorySize, SM_BYTES);
        cudaFuncSetAttribute(gemm_mma_k<true, false>,
                             cudaFuncAttributeMaxDynamicSharedMemorySize, SM_BYTES);
        cudaStreamCreateWithFlags(&sW, cudaStreamNonBlocking);
        cudaStreamCreateWithFlags(&sC, cudaStreamNonBlocking);
        cudaEventCreateWithFlags(&eIn, cudaEventDisableTiming);
        cudaEventCreateWithFlags(&eW,  cudaEventDisableTiming);
        cudaEventCreateWithFlags(&eC1, cudaEventDisableTiming);
        cudaEventCreateWithFlags(&eC2, cudaEventDisableTiming);
        inited = 1;
    }

    cudaEventRecord(eIn, 0);

    // ---- stream sW: weight transposes + x fp16 (needed only by GEMM L0) ----
    cudaStreamWaitEvent(sW, eIn, 0);
    {
        dim3 blk(32, 32);
        transpose_cvt_k<<<dim3(HH / 32, FF0 / 32), blk, 0, sW>>>(Ws0, w0t_p, FF0, HH);
        transpose_cvt_k<<<dim3(HH / 32, FF0 / 32), blk, 0, sW>>>(Wn0, w0t_p + HH * FF0, FF0, HH);
        transpose_cvt_k<<<dim3(HH / 32, HH / 32), blk, 0, sW>>>(Ws1, w1t_p, HH, HH);
        transpose_cvt_k<<<dim3(HH / 32, HH / 32), blk, 0, sW>>>(Wn1, w1t_p + HH * HH, HH, HH);
        int n4 = NN1 * FF0 / 4;
        cvt_half_k<<<(n4 + 255) / 256, 256, 0, sW>>>(x, xh_p, n4);
    }
    cudaEventRecord(eW, sW);

    // ---- stream sC: CSR builds for layers 1 and 2 ----
    cudaStreamWaitEvent(sC, eIn, 0);
    zero_deg_k<<<(NN2 + 255) / 256, 256, 0, sC>>>(deg1, NN2);
    count_deg_k<<<(EE1 + 255) / 256, 256, 0, sC>>>(dst1, deg1, EE1);
    exscan_k<<<1, 1024, 0, sC>>>(deg1, off1, cur1, NN2);
    scatter_k<<<(EE1 + 255) / 256, 256, 0, sC>>>(src1, dst1, cur1, es1, EE1);
    cudaEventRecord(eC1, sC);
    zero_deg_k<<<(NN3 + 255) / 256, 256, 0, sC>>>(deg2, NN3);
    count_deg_k<<<(EE2 + 255) / 256, 256, 0, sC>>>(dst2, deg2, EE2);
    exscan_k<<<1, 1024, 0, sC>>>(deg2, off2, cur2, NN3);
    scatter_k<<<(EE2 + 255) / 256, 256, 0, sC>>>(src2, dst2, cur2, es2, EE2);
    cudaEventRecord(eC2, sC);

    // ---- main chain: layer-0 CSR + aggregate (overlaps sW, sC) ----
    zero_deg_k<<<(NN1 + 255) / 256, 256>>>(deg0, NN1);
    count_deg_k<<<(EE0 + 255) / 256, 256>>>(dst0, deg0, EE0);
    exscan_k<<<1, 1024>>>(deg0, off0, cur0, NN1);
    scatter_k<<<(EE0 + 255) / 256, 256>>>(src0, dst0, cur0, es0, EE0);
    aggregate_k<FF0, true><<<NN1, FF0 / 4>>>(x, off0, deg0, es0, mh_p);

    cudaStreamWaitEvent(0, eW, 0);
    gemm_mma_k<true, true><<<dim3(HH / 128, NN1 / 128), 256, SM_BYTES>>>(
        xh_p, mh_p, w0t_p, w0t_p + HH * FF0, b0, h1h_p, NN1, HH, FF0);

    // ---- Layer 1 ----
    cudaStreamWaitEvent(0, eC1, 0);
    aggregate_h_k<HH><<<NN2, HH / 4>>>(h1h_p, off1, deg1, es1, mh_p);
    gemm_mma_k<true, false><<<dim3(HH / 128, NN2 / 128), 256, SM_BYTES>>>(
        h1h_p, mh_p, w1t_p, w1t_p + HH * HH, b1, h2_p, NN2, HH, HH);

    // ---- Layer 2 ----
    cudaStreamWaitEvent(0, eC2, 0);
    aggregate_k<HH, false><<<NN3, HH / 4>>>(h2_p, off2, deg2, es2, m_p);
    gemm_small_k<<<NN3, 128>>>(h2_p, m_p, Ws2, Wn2, b2, out, HH, CC);
}